// round 6
// baseline (speedup 1.0000x reference)
#include <cuda_runtime.h>
#include <math.h>

#define H_IMG 1024
#define W_IMG 1280
#define NPIX  (H_IMG * W_IMG)
#define DAMPING 1e-6
// Exact float-level equivalent of  __fsqrt_rn(d2) > 0.2f :
// largest float x0 with sqrt_rn(x0) <= 0.2f satisfies x0 = 10737419*2^-28.
#define DIST_THR2_EQ 0.040000002831220626f
#define NORM_THR_F 0.93969262078590838405f  /* cos(20 deg) */

#define NBLOCKS 288      // <= 2 CTAs/SM * 144 SMs: co-residency guaranteed
#define NTHREADS 256
#define NGROUPS (NPIX / 4)          // 327680 groups of 4 pixels
#define MAX_ITER 3

// Persistent state (no device allocation allowed).
__device__ double g_poseD[16];        // current pose, fp64, row-major 4x4
__device__ float  g_poseF[12];        // [0..8] R row-major, [9..11] t
__device__ double g_accum[28];        // 21 JtJ upper-tri, 6 JtR, 1 count
__device__ unsigned int g_arrive;     // barrier arrival counter
__device__ volatile unsigned int g_phase;  // completed-iteration counter

// ---------------------------------------------------------------------------
__global__ void icp_init(const float* __restrict__ pose10) {
    if (threadIdx.x == 0 && blockIdx.x == 0) {
        #pragma unroll
        for (int i = 0; i < 16; i++) g_poseD[i] = (double)pose10[i];
        #pragma unroll
        for (int r = 0; r < 3; r++) {
            #pragma unroll
            for (int c = 0; c < 3; c++) g_poseF[r * 3 + c] = pose10[r * 4 + c];
            g_poseF[9 + r] = pose10[r * 4 + 3];
        }
        #pragma unroll
        for (int i = 0; i < 28; i++) g_accum[i] = 0.0;
        g_arrive = 0;
        g_phase = 0;
    }
}

// ---------------------------------------------------------------------------
// Two correctly-rounded divisions px/pz, py/pz sharing ONE MUFU.RCP.
// rcp.approx + 2 Newton steps gives y ~ 1/pz to <=1ulp; Markstein correction
// then yields the correctly-rounded quotient (== __fdiv_rn) for our normal,
// well-conditioned inputs (pz in ~[0.3, 3.3]).
__device__ __forceinline__ float2 div2_rn(float px, float py, float pz) {
    float y;
    asm("rcp.approx.f32 %0, %1;" : "=f"(y) : "f"(pz));
    float e  = __fmaf_rn(-pz, y, 1.0f);
    y = __fmaf_rn(y, e, y);
    float e2 = __fmaf_rn(-pz, y, 1.0f);
    y = __fmaf_rn(y, e2, y);
    float qu = __fmul_rn(px, y);
    float ru = __fmaf_rn(-pz, qu, px);
    qu = __fmaf_rn(ru, y, qu);
    float qv = __fmul_rn(py, y);
    float rv = __fmaf_rn(-pz, qv, py);
    qv = __fmaf_rn(rv, y, qv);
    return make_float2(qu, qv);
}

// ---------------------------------------------------------------------------
// fp64 solve on one thread: LDLT 6x6, se3 exp via Taylor-in-theta^2.
__device__ void solve_update(int write_out, float* out, int out_size)
{
    double A[6][6], b[6];
    {
        int k = 0;
        for (int i = 0; i < 6; i++)
            for (int j = i; j < 6; j++) { A[i][j] = g_accum[k]; A[j][i] = g_accum[k]; k++; }
        double tr = 0.0;
        for (int i = 0; i < 6; i++) tr += A[i][i];
        for (int i = 0; i < 6; i++) A[i][i] += tr * DAMPING;
        for (int i = 0; i < 6; i++) b[i] = g_accum[21 + i];
    }
    const double count = g_accum[27];

    double L[6][6], D[6];
    for (int j = 0; j < 6; j++) {
        double dj = A[j][j];
        for (int k = 0; k < j; k++) dj -= L[j][k] * L[j][k] * D[k];
        D[j] = dj;
        L[j][j] = 1.0;
        for (int i = j + 1; i < 6; i++) {
            double v = A[i][j];
            for (int k = 0; k < j; k++) v -= L[i][k] * L[j][k] * D[k];
            L[i][j] = v / dj;
        }
    }
    double y[6];
    for (int i = 0; i < 6; i++) {
        double v = b[i];
        for (int k = 0; k < i; k++) v -= L[i][k] * y[k];
        y[i] = v;
    }
    double xi[6];
    for (int i = 5; i >= 0; i--) {
        double v = y[i] / D[i];
        for (int k = i + 1; k < 6; k++) v -= L[k][i] * xi[k];
        xi[i] = v;
    }
    for (int i = 0; i < 6; i++) xi[i] = -xi[i];

    const double w0 = xi[0], w1 = xi[1], w2 = xi[2];
    const double vx = xi[3], vy = xi[4], vz = xi[5];
    const double t2 = w0 * w0 + w1 * w1 + w2 * w2;
    double E[3][3], Jm[3][3];
    if (t2 <= 1e-16) {
        for (int i = 0; i < 3; i++)
            for (int j = 0; j < 3; j++) {
                E[i][j]  = (i == j) ? 1.0 : 0.0;
                Jm[i][j] = (i == j) ? 1.0 : 0.0;
            }
    } else {
        double cA, cB, cC;
        if (t2 < 0.25) {
            cA = 1.0 + t2 * (-1.0 / 6.0 + t2 * (1.0 / 120.0 + t2 * (-1.0 / 5040.0 +
                 t2 * (1.0 / 362880.0 + t2 * (-1.0 / 39916800.0)))));
            cB = 0.5 + t2 * (-1.0 / 24.0 + t2 * (1.0 / 720.0 + t2 * (-1.0 / 40320.0 +
                 t2 * (1.0 / 3628800.0 + t2 * (-1.0 / 479001600.0)))));
            cC = 1.0 / 6.0 + t2 * (-1.0 / 120.0 + t2 * (1.0 / 5040.0 + t2 * (-1.0 / 362880.0 +
                 t2 * (1.0 / 39916800.0 + t2 * (-1.0 / 6227020800.0)))));
        } else {
            const double th = sqrt(t2);
            const double st = sin(th), ct = cos(th);
            cA = st / th;
            cB = (1.0 - ct) / t2;
            cC = (th - st) / (t2 * th);
        }
        const double wh[3][3] = { {0.0, -w2,  w1}, { w2, 0.0, -w0}, {-w1,  w0, 0.0} };
        double wh2[3][3];
        for (int i = 0; i < 3; i++)
            for (int j = 0; j < 3; j++) {
                double acc = 0.0;
                for (int k = 0; k < 3; k++) acc += wh[i][k] * wh[k][j];
                wh2[i][j] = acc;
            }
        for (int i = 0; i < 3; i++)
            for (int j = 0; j < 3; j++) {
                const double eye = (i == j) ? 1.0 : 0.0;
                E[i][j]  = eye + cA * wh[i][j] + cB * wh2[i][j];
                Jm[i][j] = eye + cB * wh[i][j] + cC * wh2[i][j];
            }
    }
    double T[16];
    for (int i = 0; i < 3; i++) {
        for (int j = 0; j < 3; j++) T[i * 4 + j] = E[i][j];
        T[i * 4 + 3] = Jm[i][0] * vx + Jm[i][1] * vy + Jm[i][2] * vz;
    }
    T[12] = 0.0; T[13] = 0.0; T[14] = 0.0; T[15] = 1.0;

    double P[16];
    for (int i = 0; i < 4; i++)
        for (int j = 0; j < 4; j++) {
            double acc = 0.0;
            for (int k = 0; k < 4; k++) acc += T[i * 4 + k] * g_poseD[k * 4 + j];
            P[i * 4 + j] = acc;
        }
    for (int i = 0; i < 16; i++) g_poseD[i] = P[i];
    for (int r = 0; r < 3; r++) {
        for (int c = 0; c < 3; c++) g_poseF[r * 3 + c] = (float)P[r * 4 + c];
        g_poseF[9 + r] = (float)P[r * 4 + 3];
    }

    if (write_out) {
        for (int i = 0; i < 16 && i < out_size; i++) out[i] = (float)P[i];
        if (out_size >= 17) out[16] = (float)(count / (double)NPIX);
    }
    for (int i = 0; i < 28; i++) g_accum[i] = 0.0;
}

// ---------------------------------------------------------------------------
// Per-pixel body: branchless accumulate; exact-rounding ops keep the
// round(u/v) discretization identical under --use_fast_math.
__device__ __forceinline__ void px_body(
    float x, float y, float z, float nx, float ny, float nz,
    const float* __restrict__ v1d, const float* __restrict__ n1d,
    float fx, float fy, float cx, float cy,
    float R00, float R01, float R02, float R10, float R11, float R12,
    float R20, float R21, float R22, float tx, float ty, float tz,
    float* s)
{
    const float px = __fmaf_rn(x, R00, __fmaf_rn(y, R01, __fmaf_rn(z, R02, tx)));
    const float py = __fmaf_rn(x, R10, __fmaf_rn(y, R11, __fmaf_rn(z, R12, ty)));
    const float pz = __fmaf_rn(x, R20, __fmaf_rn(y, R21, __fmaf_rn(z, R22, tz)));

    const float qx = __fmaf_rn(nx, R00, __fmaf_rn(ny, R01, __fmul_rn(nz, R02)));
    const float qy = __fmaf_rn(nx, R10, __fmaf_rn(ny, R11, __fmul_rn(nz, R12)));
    const float qz = __fmaf_rn(nx, R20, __fmaf_rn(ny, R21, __fmul_rn(nz, R22)));

    const float2 q2 = div2_rn(px, py, pz);   // == __fdiv_rn(px,pz), __fdiv_rn(py,pz)
    const float u = __fadd_rn(__fmul_rn(q2.x, fx), cx);
    const float v = __fadd_rn(__fmul_rn(q2.y, fy), cy);
    const bool inview = (u > 0.f) && (u < (float)(W_IMG - 1)) &&
                        (v > 0.f) && (v < (float)(H_IMG - 1));

    const float uif = fminf(fmaxf(rintf(u), 0.f), (float)(W_IMG - 1));
    const float vif = fminf(fmaxf(rintf(v), 0.f), (float)(H_IMG - 1));
    const int g = (int)vif * W_IMG + (int)uif;

    const float ax = v1d[3 * g + 0];
    const float ay = v1d[3 * g + 1];
    const float az = v1d[3 * g + 2];
    const float bx = n1d[3 * g + 0];
    const float by = n1d[3 * g + 1];
    const float bz = n1d[3 * g + 2];

    const float dx = __fadd_rn(px, -ax);
    const float dy = __fadd_rn(py, -ay);
    const float dz = __fadd_rn(pz, -az);
    const float d2 = __fmaf_rn(dx, dx, __fmaf_rn(dy, dy, __fmul_rn(dz, dz)));
    const float ndot = __fmaf_rn(qx, bx, __fmaf_rn(qy, by, __fmul_rn(qz, bz)));

    // d2 > DIST_THR2_EQ  <=>  __fsqrt_rn(d2) > 0.2f  (exact equivalence)
    const bool valid = inview && !(d2 > DIST_THR2_EQ) &&
                       (z > 0.f) && (az > 0.f) && (ndot > NORM_THR_F);

    float r = __fmaf_rn(bx, dx, __fmaf_rn(by, dy, __fmul_rn(bz, dz)));
    float J[6];
    J[0] = __fadd_rn(__fmul_rn(py, bz), -__fmul_rn(pz, by));
    J[1] = __fadd_rn(__fmul_rn(pz, bx), -__fmul_rn(px, bz));
    J[2] = __fadd_rn(__fmul_rn(px, by), -__fmul_rn(py, bx));
    J[3] = bx; J[4] = by; J[5] = bz;
    if (!valid) {
        r = 0.f;
        #pragma unroll
        for (int i = 0; i < 6; i++) J[i] = 0.f;
    }
    int k = 0;
    #pragma unroll
    for (int i = 0; i < 6; i++)
        #pragma unroll
        for (int j = i; j < 6; j++) { s[k] = __fmaf_rn(J[i], J[j], s[k]); k++; }
    #pragma unroll
    for (int i = 0; i < 6; i++) s[21 + i] = __fmaf_rn(J[i], r, s[21 + i]);
    if (valid) s[27] += 1.f;
}

// ---------------------------------------------------------------------------
__global__ __launch_bounds__(NTHREADS, 2)
void icp_persistent(const float* __restrict__ v0d, const float* __restrict__ v1d,
                    const float* __restrict__ n0d, const float* __restrict__ n1d,
                    const float* __restrict__ Km,
                    float* __restrict__ out, int out_size)
{
    const float fx = Km[0], cx = Km[2], fy = Km[4], cy = Km[5];
    const int tglob = blockIdx.x * NTHREADS + threadIdx.x;
    const int ntot  = NBLOCKS * NTHREADS;

    __shared__ double sh[28];
    __shared__ unsigned int s_last;

    for (int it = 0; it < MAX_ITER; ++it) {
        const float R00 = g_poseF[0], R01 = g_poseF[1], R02 = g_poseF[2];
        const float R10 = g_poseF[3], R11 = g_poseF[4], R12 = g_poseF[5];
        const float R20 = g_poseF[6], R21 = g_poseF[7], R22 = g_poseF[8];
        const float tx  = g_poseF[9], ty  = g_poseF[10], tz = g_poseF[11];

        float s[28];
        #pragma unroll
        for (int i = 0; i < 28; i++) s[i] = 0.f;

        for (int t = tglob; t < NGROUPS; t += ntot) {
            const float4* v0q = (const float4*)(v0d) + 3 * t;
            const float4* n0q = (const float4*)(n0d) + 3 * t;
            const float4 a0 = v0q[0], a1 = v0q[1], a2 = v0q[2];
            const float4 b0 = n0q[0], b1 = n0q[1], b2 = n0q[2];
            px_body(a0.x, a0.y, a0.z, b0.x, b0.y, b0.z, v1d, n1d, fx, fy, cx, cy,
                    R00, R01, R02, R10, R11, R12, R20, R21, R22, tx, ty, tz, s);
            px_body(a0.w, a1.x, a1.y, b0.w, b1.x, b1.y, v1d, n1d, fx, fy, cx, cy,
                    R00, R01, R02, R10, R11, R12, R20, R21, R22, tx, ty, tz, s);
            px_body(a1.z, a1.w, a2.x, b1.z, b1.w, b2.x, v1d, n1d, fx, fy, cx, cy,
                    R00, R01, R02, R10, R11, R12, R20, R21, R22, tx, ty, tz, s);
            px_body(a2.y, a2.z, a2.w, b2.y, b2.z, b2.w, v1d, n1d, fx, fy, cx, cy,
                    R00, R01, R02, R10, R11, R12, R20, R21, R22, tx, ty, tz, s);
        }

        #pragma unroll
        for (int i = 0; i < 28; i++) {
            #pragma unroll
            for (int o = 16; o > 0; o >>= 1)
                s[i] += __shfl_down_sync(0xffffffffu, s[i], o);
        }

        if (threadIdx.x < 28) sh[threadIdx.x] = 0.0;
        __syncthreads();
        if ((threadIdx.x & 31) == 0) {
            #pragma unroll
            for (int i = 0; i < 28; i++) atomicAdd(&sh[i], (double)s[i]);
        }
        __syncthreads();
        if (threadIdx.x < 28) atomicAdd(&g_accum[threadIdx.x], sh[threadIdx.x]);

        // ---- grid barrier + inline solve by the last-arriving CTA ----
        if (threadIdx.x == 0) {
            __threadfence();
            s_last = atomicAdd(&g_arrive, 1u);
        }
        __syncthreads();
        const bool is_solver = (s_last == (unsigned)(gridDim.x * (it + 1) - 1));
        if (is_solver && threadIdx.x == 0) {
            solve_update(it == MAX_ITER - 1 ? 1 : 0, out, out_size);
            __threadfence();
            g_phase = it + 1;   // release
        }
        if (it < MAX_ITER - 1) {
            if (threadIdx.x == 0) {
                while (g_phase < (unsigned)(it + 1)) { __nanosleep(200); }
            }
            __syncthreads();
            __threadfence();
        }
    }
}

// ---------------------------------------------------------------------------
extern "C" void kernel_launch(void* const* d_in, const int* in_sizes, int n_in,
                              void* d_out, int out_size)
{
    const float* pose10 = (const float*)d_in[0];  // 16
    const float* v0     = (const float*)d_in[1];  // H*W*3
    const float* v1     = (const float*)d_in[2];  // H*W*3
    const float* n0     = (const float*)d_in[3];  // H*W*3
    const float* n1     = (const float*)d_in[4];  // H*W*3
    const float* K      = (const float*)d_in[5];  // 9
    float* out = (float*)d_out;

    icp_init<<<1, 32>>>(pose10);
    icp_persistent<<<NBLOCKS, NTHREADS>>>(v0, v1, n0, n1, K, out, out_size);
}

// round 7
// speedup vs baseline: 1.0046x; 1.0046x over previous
#include <cuda_runtime.h>
#include <math.h>

#define H_IMG 1024
#define W_IMG 1280
#define NPIX  (H_IMG * W_IMG)
#define DAMPING 1e-6
// Exact float-level equivalent of  __fsqrt_rn(d2) > 0.2f :
// largest float x0 with sqrt_rn(x0) <= 0.2f satisfies x0 = 10737419*2^-28.
#define DIST_THR2_EQ 0.040000002831220626f
#define NORM_THR_F 0.93969262078590838405f  /* cos(20 deg) */

#define NBLOCKS 288      // <= 2 CTAs/SM * 144 SMs: co-residency guaranteed
#define NTHREADS 256
#define NGROUPS (NPIX / 4)          // 327680 groups of 4 pixels
#define MAX_ITER 3

// Persistent state (no device allocation allowed).
__device__ double g_poseD[16];        // current pose, fp64, row-major 4x4
__device__ float  g_poseF[12];        // [0..8] R row-major, [9..11] t
__device__ double g_accum[28];        // 21 JtJ upper-tri, 6 JtR, 1 count
__device__ unsigned int g_arrive;     // barrier arrival counter
__device__ volatile unsigned int g_phase;  // completed-iteration counter

// ---------------------------------------------------------------------------
__global__ void icp_init(const float* __restrict__ pose10) {
    if (threadIdx.x == 0 && blockIdx.x == 0) {
        #pragma unroll
        for (int i = 0; i < 16; i++) g_poseD[i] = (double)pose10[i];
        #pragma unroll
        for (int r = 0; r < 3; r++) {
            #pragma unroll
            for (int c = 0; c < 3; c++) g_poseF[r * 3 + c] = pose10[r * 4 + c];
            g_poseF[9 + r] = pose10[r * 4 + 3];
        }
        #pragma unroll
        for (int i = 0; i < 28; i++) g_accum[i] = 0.0;
        g_arrive = 0;
        g_phase = 0;
    }
}

// ---------------------------------------------------------------------------
// Two correctly-rounded divisions px/pz, py/pz sharing ONE MUFU.RCP.
// (== __fdiv_rn for our normal, well-conditioned inputs, pz in ~[0.3, 3.3])
__device__ __forceinline__ float2 div2_rn(float px, float py, float pz) {
    float y;
    asm("rcp.approx.f32 %0, %1;" : "=f"(y) : "f"(pz));
    float e  = __fmaf_rn(-pz, y, 1.0f);
    y = __fmaf_rn(y, e, y);
    float e2 = __fmaf_rn(-pz, y, 1.0f);
    y = __fmaf_rn(y, e2, y);
    float qu = __fmul_rn(px, y);
    float ru = __fmaf_rn(-pz, qu, px);
    qu = __fmaf_rn(ru, y, qu);
    float qv = __fmul_rn(py, y);
    float rv = __fmaf_rn(-pz, qv, py);
    qv = __fmaf_rn(rv, y, qv);
    return make_float2(qu, qv);
}

// ---------------------------------------------------------------------------
// fp64 solve on one thread: LDLT 6x6, se3 exp via Taylor-in-theta^2.
__device__ void solve_update(int write_out, float* out, int out_size)
{
    double A[6][6], b[6];
    {
        int k = 0;
        for (int i = 0; i < 6; i++)
            for (int j = i; j < 6; j++) { A[i][j] = g_accum[k]; A[j][i] = g_accum[k]; k++; }
        double tr = 0.0;
        for (int i = 0; i < 6; i++) tr += A[i][i];
        for (int i = 0; i < 6; i++) A[i][i] += tr * DAMPING;
        for (int i = 0; i < 6; i++) b[i] = g_accum[21 + i];
    }
    const double count = g_accum[27];

    double L[6][6], D[6];
    for (int j = 0; j < 6; j++) {
        double dj = A[j][j];
        for (int k = 0; k < j; k++) dj -= L[j][k] * L[j][k] * D[k];
        D[j] = dj;
        L[j][j] = 1.0;
        for (int i = j + 1; i < 6; i++) {
            double v = A[i][j];
            for (int k = 0; k < j; k++) v -= L[i][k] * L[j][k] * D[k];
            L[i][j] = v / dj;
        }
    }
    double y[6];
    for (int i = 0; i < 6; i++) {
        double v = b[i];
        for (int k = 0; k < i; k++) v -= L[i][k] * y[k];
        y[i] = v;
    }
    double xi[6];
    for (int i = 5; i >= 0; i--) {
        double v = y[i] / D[i];
        for (int k = i + 1; k < 6; k++) v -= L[k][i] * xi[k];
        xi[i] = v;
    }
    for (int i = 0; i < 6; i++) xi[i] = -xi[i];

    const double w0 = xi[0], w1 = xi[1], w2 = xi[2];
    const double vx = xi[3], vy = xi[4], vz = xi[5];
    const double t2 = w0 * w0 + w1 * w1 + w2 * w2;
    double E[3][3], Jm[3][3];
    if (t2 <= 1e-16) {
        for (int i = 0; i < 3; i++)
            for (int j = 0; j < 3; j++) {
                E[i][j]  = (i == j) ? 1.0 : 0.0;
                Jm[i][j] = (i == j) ? 1.0 : 0.0;
            }
    } else {
        double cA, cB, cC;
        if (t2 < 0.25) {
            cA = 1.0 + t2 * (-1.0 / 6.0 + t2 * (1.0 / 120.0 + t2 * (-1.0 / 5040.0 +
                 t2 * (1.0 / 362880.0 + t2 * (-1.0 / 39916800.0)))));
            cB = 0.5 + t2 * (-1.0 / 24.0 + t2 * (1.0 / 720.0 + t2 * (-1.0 / 40320.0 +
                 t2 * (1.0 / 3628800.0 + t2 * (-1.0 / 479001600.0)))));
            cC = 1.0 / 6.0 + t2 * (-1.0 / 120.0 + t2 * (1.0 / 5040.0 + t2 * (-1.0 / 362880.0 +
                 t2 * (1.0 / 39916800.0 + t2 * (-1.0 / 6227020800.0)))));
        } else {
            const double th = sqrt(t2);
            const double st = sin(th), ct = cos(th);
            cA = st / th;
            cB = (1.0 - ct) / t2;
            cC = (th - st) / (t2 * th);
        }
        const double wh[3][3] = { {0.0, -w2,  w1}, { w2, 0.0, -w0}, {-w1,  w0, 0.0} };
        double wh2[3][3];
        for (int i = 0; i < 3; i++)
            for (int j = 0; j < 3; j++) {
                double acc = 0.0;
                for (int k = 0; k < 3; k++) acc += wh[i][k] * wh[k][j];
                wh2[i][j] = acc;
            }
        for (int i = 0; i < 3; i++)
            for (int j = 0; j < 3; j++) {
                const double eye = (i == j) ? 1.0 : 0.0;
                E[i][j]  = eye + cA * wh[i][j] + cB * wh2[i][j];
                Jm[i][j] = eye + cB * wh[i][j] + cC * wh2[i][j];
            }
    }
    double T[16];
    for (int i = 0; i < 3; i++) {
        for (int j = 0; j < 3; j++) T[i * 4 + j] = E[i][j];
        T[i * 4 + 3] = Jm[i][0] * vx + Jm[i][1] * vy + Jm[i][2] * vz;
    }
    T[12] = 0.0; T[13] = 0.0; T[14] = 0.0; T[15] = 1.0;

    double P[16];
    for (int i = 0; i < 4; i++)
        for (int j = 0; j < 4; j++) {
            double acc = 0.0;
            for (int k = 0; k < 4; k++) acc += T[i * 4 + k] * g_poseD[k * 4 + j];
            P[i * 4 + j] = acc;
        }
    for (int i = 0; i < 16; i++) g_poseD[i] = P[i];
    for (int r = 0; r < 3; r++) {
        for (int c = 0; c < 3; c++) g_poseF[r * 3 + c] = (float)P[r * 4 + c];
        g_poseF[9 + r] = (float)P[r * 4 + 3];
    }

    if (write_out) {
        for (int i = 0; i < 16 && i < out_size; i++) out[i] = (float)P[i];
        if (out_size >= 17) out[16] = (float)(count / (double)NPIX);
    }
    for (int i = 0; i < 28; i++) g_accum[i] = 0.0;
}

// ---------------------------------------------------------------------------
// Persistent kernel: 3 ICP iterations in one launch with a software grid
// barrier. Group body is software-pipelined into 3 phases so all 24 gather
// LDGs per thread-group issue back-to-back (high MLP -> hidden latency).
__global__ __launch_bounds__(NTHREADS, 2)
void icp_persistent(const float* __restrict__ v0d, const float* __restrict__ v1d,
                    const float* __restrict__ n0d, const float* __restrict__ n1d,
                    const float* __restrict__ Km,
                    float* __restrict__ out, int out_size)
{
    const float fx = Km[0], cx = Km[2], fy = Km[4], cy = Km[5];
    const int tglob = blockIdx.x * NTHREADS + threadIdx.x;
    const int ntot  = NBLOCKS * NTHREADS;

    __shared__ double sh[28];
    __shared__ unsigned int s_last;

    for (int it = 0; it < MAX_ITER; ++it) {
        const float R00 = g_poseF[0], R01 = g_poseF[1], R02 = g_poseF[2];
        const float R10 = g_poseF[3], R11 = g_poseF[4], R12 = g_poseF[5];
        const float R20 = g_poseF[6], R21 = g_poseF[7], R22 = g_poseF[8];
        const float tx  = g_poseF[9], ty  = g_poseF[10], tz = g_poseF[11];

        float s[28];
        #pragma unroll
        for (int i = 0; i < 28; i++) s[i] = 0.f;

        for (int t = tglob; t < NGROUPS; t += ntot) {
            const float4* v0q = (const float4*)(v0d) + 3 * t;
            const float4* n0q = (const float4*)(n0d) + 3 * t;
            const float4 a0 = v0q[0], a1 = v0q[1], a2 = v0q[2];
            const float4 b0 = n0q[0], b1 = n0q[1], b2 = n0q[2];

            const float X[4]  = {a0.x, a0.w, a1.z, a2.y};
            const float Y[4]  = {a0.y, a1.x, a1.w, a2.z};
            const float Z[4]  = {a0.z, a1.y, a2.x, a2.w};
            const float NXv[4] = {b0.x, b0.w, b1.z, b2.y};
            const float NYv[4] = {b0.y, b1.x, b1.w, b2.z};
            const float NZv[4] = {b0.z, b1.y, b2.x, b2.w};

            // ---- Phase A: transforms + projection + gather index (no loads)
            float PX[4], PY[4], PZ[4], QX[4], QY[4], QZ[4];
            int   G[4];
            bool  INV[4];
            #pragma unroll
            for (int i = 0; i < 4; i++) {
                const float x = X[i], y = Y[i], z = Z[i];
                PX[i] = __fmaf_rn(x, R00, __fmaf_rn(y, R01, __fmaf_rn(z, R02, tx)));
                PY[i] = __fmaf_rn(x, R10, __fmaf_rn(y, R11, __fmaf_rn(z, R12, ty)));
                PZ[i] = __fmaf_rn(x, R20, __fmaf_rn(y, R21, __fmaf_rn(z, R22, tz)));
                QX[i] = __fmaf_rn(NXv[i], R00, __fmaf_rn(NYv[i], R01, __fmul_rn(NZv[i], R02)));
                QY[i] = __fmaf_rn(NXv[i], R10, __fmaf_rn(NYv[i], R11, __fmul_rn(NZv[i], R12)));
                QZ[i] = __fmaf_rn(NXv[i], R20, __fmaf_rn(NYv[i], R21, __fmul_rn(NZv[i], R22)));
                const float2 q2 = div2_rn(PX[i], PY[i], PZ[i]);
                const float u = __fadd_rn(__fmul_rn(q2.x, fx), cx);
                const float v = __fadd_rn(__fmul_rn(q2.y, fy), cy);
                INV[i] = (u > 0.f) && (u < (float)(W_IMG - 1)) &&
                         (v > 0.f) && (v < (float)(H_IMG - 1));
                const float uif = fminf(fmaxf(rintf(u), 0.f), (float)(W_IMG - 1));
                const float vif = fminf(fmaxf(rintf(v), 0.f), (float)(H_IMG - 1));
                G[i] = (int)vif * W_IMG + (int)uif;
            }

            // ---- Phase B: 24 gather loads issued back-to-back (max MLP)
            float AX[4], AY[4], AZ[4], BX[4], BY[4], BZ[4];
            #pragma unroll
            for (int i = 0; i < 4; i++) {
                AX[i] = __ldg(v1d + 3 * G[i] + 0);
                AY[i] = __ldg(v1d + 3 * G[i] + 1);
                AZ[i] = __ldg(v1d + 3 * G[i] + 2);
                BX[i] = __ldg(n1d + 3 * G[i] + 0);
                BY[i] = __ldg(n1d + 3 * G[i] + 1);
                BZ[i] = __ldg(n1d + 3 * G[i] + 2);
            }

            // ---- Phase C: residual/Jacobian + branchless accumulate
            #pragma unroll
            for (int i = 0; i < 4; i++) {
                const float px = PX[i], py = PY[i], pz = PZ[i];
                const float bx = BX[i], by = BY[i], bz = BZ[i];
                const float dx = __fadd_rn(px, -AX[i]);
                const float dy = __fadd_rn(py, -AY[i]);
                const float dz = __fadd_rn(pz, -AZ[i]);
                const float d2 = __fmaf_rn(dx, dx, __fmaf_rn(dy, dy, __fmul_rn(dz, dz)));
                const float ndot = __fmaf_rn(QX[i], bx, __fmaf_rn(QY[i], by, __fmul_rn(QZ[i], bz)));

                const bool valid = INV[i] && !(d2 > DIST_THR2_EQ) &&
                                   (Z[i] > 0.f) && (AZ[i] > 0.f) && (ndot > NORM_THR_F);

                float r = __fmaf_rn(bx, dx, __fmaf_rn(by, dy, __fmul_rn(bz, dz)));
                float J[6];
                J[0] = __fadd_rn(__fmul_rn(py, bz), -__fmul_rn(pz, by));
                J[1] = __fadd_rn(__fmul_rn(pz, bx), -__fmul_rn(px, bz));
                J[2] = __fadd_rn(__fmul_rn(px, by), -__fmul_rn(py, bx));
                J[3] = bx; J[4] = by; J[5] = bz;
                if (!valid) {
                    r = 0.f;
                    #pragma unroll
                    for (int q = 0; q < 6; q++) J[q] = 0.f;
                }
                int k = 0;
                #pragma unroll
                for (int a = 0; a < 6; a++)
                    #pragma unroll
                    for (int c = a; c < 6; c++) { s[k] = __fmaf_rn(J[a], J[c], s[k]); k++; }
                #pragma unroll
                for (int a = 0; a < 6; a++) s[21 + a] = __fmaf_rn(J[a], r, s[21 + a]);
                if (valid) s[27] += 1.f;
            }
        }

        // warp reduction
        #pragma unroll
        for (int i = 0; i < 28; i++) {
            #pragma unroll
            for (int o = 16; o > 0; o >>= 1)
                s[i] += __shfl_down_sync(0xffffffffu, s[i], o);
        }

        if (threadIdx.x < 28) sh[threadIdx.x] = 0.0;
        __syncthreads();
        if ((threadIdx.x & 31) == 0) {
            #pragma unroll
            for (int i = 0; i < 28; i++) atomicAdd(&sh[i], (double)s[i]);
        }
        __syncthreads();
        if (threadIdx.x < 28) atomicAdd(&g_accum[threadIdx.x], sh[threadIdx.x]);

        // ---- grid barrier + inline solve by the last-arriving CTA ----
        if (threadIdx.x == 0) {
            __threadfence();
            s_last = atomicAdd(&g_arrive, 1u);
        }
        __syncthreads();
        const bool is_solver = (s_last == (unsigned)(gridDim.x * (it + 1) - 1));
        if (is_solver && threadIdx.x == 0) {
            solve_update(it == MAX_ITER - 1 ? 1 : 0, out, out_size);
            __threadfence();
            g_phase = it + 1;   // release
        }
        if (it < MAX_ITER - 1) {
            if (threadIdx.x == 0) {
                while (g_phase < (unsigned)(it + 1)) { __nanosleep(200); }
            }
            __syncthreads();
            __threadfence();
        }
    }
}

// ---------------------------------------------------------------------------
extern "C" void kernel_launch(void* const* d_in, const int* in_sizes, int n_in,
                              void* d_out, int out_size)
{
    const float* pose10 = (const float*)d_in[0];  // 16
    const float* v0     = (const float*)d_in[1];  // H*W*3
    const float* v1     = (const float*)d_in[2];  // H*W*3
    const float* n0     = (const float*)d_in[3];  // H*W*3
    const float* n1     = (const float*)d_in[4];  // H*W*3
    const float* K      = (const float*)d_in[5];  // 9
    float* out = (float*)d_out;

    icp_init<<<1, 32>>>(pose10);
    icp_persistent<<<NBLOCKS, NTHREADS>>>(v0, v1, n0, n1, K, out, out_size);
}

// round 8
// speedup vs baseline: 1.0241x; 1.0195x over previous
#include <cuda_runtime.h>
#include <math.h>

#define H_IMG 1024
#define W_IMG 1280
#define NPIX  (H_IMG * W_IMG)
#define DAMPING 1e-6
// Exact float-level equivalent of  __fsqrt_rn(d2) > 0.2f
#define DIST_THR2_EQ 0.040000002831220626f
#define NORM_THR_F 0.93969262078590838405f  /* cos(20 deg) */

#define NBLOCKS 288      // <= 2 CTAs/SM * 144 SMs: co-residency guaranteed
#define NTHREADS 256
#define TILE_PX 1024     // 256 threads * 4 px, lane-consecutive ownership
#define NTILES (NPIX / TILE_PX)   // 1280
#define MAX_ITER 3

// Persistent state (no device allocation allowed).
__device__ double g_poseD[16];
__device__ float  g_poseF[12];
__device__ double g_accum[28];
__device__ unsigned int g_arrive;
__device__ volatile unsigned int g_phase;
__device__ unsigned int g_work[MAX_ITER];   // work-stealing tile counters

// ---------------------------------------------------------------------------
__global__ void icp_init(const float* __restrict__ pose10) {
    if (threadIdx.x == 0 && blockIdx.x == 0) {
        #pragma unroll
        for (int i = 0; i < 16; i++) g_poseD[i] = (double)pose10[i];
        #pragma unroll
        for (int r = 0; r < 3; r++) {
            #pragma unroll
            for (int c = 0; c < 3; c++) g_poseF[r * 3 + c] = pose10[r * 4 + c];
            g_poseF[9 + r] = pose10[r * 4 + 3];
        }
        #pragma unroll
        for (int i = 0; i < 28; i++) g_accum[i] = 0.0;
        g_arrive = 0;
        g_phase = 0;
        #pragma unroll
        for (int i = 0; i < MAX_ITER; i++) g_work[i] = 0;
    }
}

// ---------------------------------------------------------------------------
// Two correctly-rounded divisions sharing ONE MUFU.RCP (== __fdiv_rn here).
__device__ __forceinline__ float2 div2_rn(float px, float py, float pz) {
    float y;
    asm("rcp.approx.f32 %0, %1;" : "=f"(y) : "f"(pz));
    float e  = __fmaf_rn(-pz, y, 1.0f);
    y = __fmaf_rn(y, e, y);
    float e2 = __fmaf_rn(-pz, y, 1.0f);
    y = __fmaf_rn(y, e2, y);
    float qu = __fmul_rn(px, y);
    float ru = __fmaf_rn(-pz, qu, px);
    qu = __fmaf_rn(ru, y, qu);
    float qv = __fmul_rn(py, y);
    float rv = __fmaf_rn(-pz, qv, py);
    qv = __fmaf_rn(rv, y, qv);
    return make_float2(qu, qv);
}

// ---------------------------------------------------------------------------
// fp64 solve on one thread: LDLT 6x6, se3 exp via Taylor-in-theta^2.
__device__ void solve_update(int write_out, float* out, int out_size)
{
    double A[6][6], b[6];
    {
        int k = 0;
        for (int i = 0; i < 6; i++)
            for (int j = i; j < 6; j++) { A[i][j] = g_accum[k]; A[j][i] = g_accum[k]; k++; }
        double tr = 0.0;
        for (int i = 0; i < 6; i++) tr += A[i][i];
        for (int i = 0; i < 6; i++) A[i][i] += tr * DAMPING;
        for (int i = 0; i < 6; i++) b[i] = g_accum[21 + i];
    }
    const double count = g_accum[27];

    double L[6][6], D[6];
    for (int j = 0; j < 6; j++) {
        double dj = A[j][j];
        for (int k = 0; k < j; k++) dj -= L[j][k] * L[j][k] * D[k];
        D[j] = dj;
        L[j][j] = 1.0;
        for (int i = j + 1; i < 6; i++) {
            double v = A[i][j];
            for (int k = 0; k < j; k++) v -= L[i][k] * L[j][k] * D[k];
            L[i][j] = v / dj;
        }
    }
    double y[6];
    for (int i = 0; i < 6; i++) {
        double v = b[i];
        for (int k = 0; k < i; k++) v -= L[i][k] * y[k];
        y[i] = v;
    }
    double xi[6];
    for (int i = 5; i >= 0; i--) {
        double v = y[i] / D[i];
        for (int k = i + 1; k < 6; k++) v -= L[k][i] * xi[k];
        xi[i] = v;
    }
    for (int i = 0; i < 6; i++) xi[i] = -xi[i];

    const double w0 = xi[0], w1 = xi[1], w2 = xi[2];
    const double vx = xi[3], vy = xi[4], vz = xi[5];
    const double t2 = w0 * w0 + w1 * w1 + w2 * w2;
    double E[3][3], Jm[3][3];
    if (t2 <= 1e-16) {
        for (int i = 0; i < 3; i++)
            for (int j = 0; j < 3; j++) {
                E[i][j]  = (i == j) ? 1.0 : 0.0;
                Jm[i][j] = (i == j) ? 1.0 : 0.0;
            }
    } else {
        double cA, cB, cC;
        if (t2 < 0.25) {
            cA = 1.0 + t2 * (-1.0 / 6.0 + t2 * (1.0 / 120.0 + t2 * (-1.0 / 5040.0 +
                 t2 * (1.0 / 362880.0 + t2 * (-1.0 / 39916800.0)))));
            cB = 0.5 + t2 * (-1.0 / 24.0 + t2 * (1.0 / 720.0 + t2 * (-1.0 / 40320.0 +
                 t2 * (1.0 / 3628800.0 + t2 * (-1.0 / 479001600.0)))));
            cC = 1.0 / 6.0 + t2 * (-1.0 / 120.0 + t2 * (1.0 / 5040.0 + t2 * (-1.0 / 362880.0 +
                 t2 * (1.0 / 39916800.0 + t2 * (-1.0 / 6227020800.0)))));
        } else {
            const double th = sqrt(t2);
            const double st = sin(th), ct = cos(th);
            cA = st / th;
            cB = (1.0 - ct) / t2;
            cC = (th - st) / (t2 * th);
        }
        const double wh[3][3] = { {0.0, -w2,  w1}, { w2, 0.0, -w0}, {-w1,  w0, 0.0} };
        double wh2[3][3];
        for (int i = 0; i < 3; i++)
            for (int j = 0; j < 3; j++) {
                double acc = 0.0;
                for (int k = 0; k < 3; k++) acc += wh[i][k] * wh[k][j];
                wh2[i][j] = acc;
            }
        for (int i = 0; i < 3; i++)
            for (int j = 0; j < 3; j++) {
                const double eye = (i == j) ? 1.0 : 0.0;
                E[i][j]  = eye + cA * wh[i][j] + cB * wh2[i][j];
                Jm[i][j] = eye + cB * wh[i][j] + cC * wh2[i][j];
            }
    }
    double T[16];
    for (int i = 0; i < 3; i++) {
        for (int j = 0; j < 3; j++) T[i * 4 + j] = E[i][j];
        T[i * 4 + 3] = Jm[i][0] * vx + Jm[i][1] * vy + Jm[i][2] * vz;
    }
    T[12] = 0.0; T[13] = 0.0; T[14] = 0.0; T[15] = 1.0;

    double P[16];
    for (int i = 0; i < 4; i++)
        for (int j = 0; j < 4; j++) {
            double acc = 0.0;
            for (int k = 0; k < 4; k++) acc += T[i * 4 + k] * g_poseD[k * 4 + j];
            P[i * 4 + j] = acc;
        }
    for (int i = 0; i < 16; i++) g_poseD[i] = P[i];
    for (int r = 0; r < 3; r++) {
        for (int c = 0; c < 3; c++) g_poseF[r * 3 + c] = (float)P[r * 4 + c];
        g_poseF[9 + r] = (float)P[r * 4 + 3];
    }

    if (write_out) {
        for (int i = 0; i < 16 && i < out_size; i++) out[i] = (float)P[i];
        if (out_size >= 17) out[16] = (float)(count / (double)NPIX);
    }
    for (int i = 0; i < 28; i++) g_accum[i] = 0.0;
}

// ---------------------------------------------------------------------------
// Persistent kernel: 3 ICP iterations, one launch. Work-stealing tiles of
// 1024 px; within a tile each thread owns lane-consecutive pixels so EVERY
// warp-LDG (stream and gather) spans ~3 cache lines instead of 12.
__global__ __launch_bounds__(NTHREADS, 2)
void icp_persistent(const float* __restrict__ v0d, const float* __restrict__ v1d,
                    const float* __restrict__ n0d, const float* __restrict__ n1d,
                    const float* __restrict__ Km,
                    float* __restrict__ out, int out_size)
{
    const float fx = Km[0], cx = Km[2], fy = Km[4], cy = Km[5];

    __shared__ double sh[28];
    __shared__ unsigned int s_last;
    __shared__ int s_tile;

    for (int it = 0; it < MAX_ITER; ++it) {
        const float R00 = g_poseF[0], R01 = g_poseF[1], R02 = g_poseF[2];
        const float R10 = g_poseF[3], R11 = g_poseF[4], R12 = g_poseF[5];
        const float R20 = g_poseF[6], R21 = g_poseF[7], R22 = g_poseF[8];
        const float tx  = g_poseF[9], ty  = g_poseF[10], tz = g_poseF[11];

        float s[28];
        #pragma unroll
        for (int i = 0; i < 28; i++) s[i] = 0.f;

        for (;;) {
            __syncthreads();
            if (threadIdx.x == 0)
                s_tile = (int)atomicAdd(&g_work[it], 1u);
            __syncthreads();
            const int tile = s_tile;
            if (tile >= NTILES) break;

            const int base = tile * TILE_PX + threadIdx.x;   // lane-consecutive

            // Phase A: stream loads (24 scalar LDG, each warp-LDG = 3 lines)
            float X[4], Y[4], Z[4], NX[4], NY[4], NZ[4];
            #pragma unroll
            for (int k = 0; k < 4; k++) {
                const int p = base + k * NTHREADS;
                X[k]  = __ldg(v0d + 3 * p + 0);
                Y[k]  = __ldg(v0d + 3 * p + 1);
                Z[k]  = __ldg(v0d + 3 * p + 2);
                NX[k] = __ldg(n0d + 3 * p + 0);
                NY[k] = __ldg(n0d + 3 * p + 1);
                NZ[k] = __ldg(n0d + 3 * p + 2);
            }

            // Phase B: transforms + projection + gather index
            float PX[4], PY[4], PZ[4], QX[4], QY[4], QZ[4];
            int   G[4];
            bool  INV[4];
            #pragma unroll
            for (int k = 0; k < 4; k++) {
                const float x = X[k], y = Y[k], z = Z[k];
                PX[k] = __fmaf_rn(x, R00, __fmaf_rn(y, R01, __fmaf_rn(z, R02, tx)));
                PY[k] = __fmaf_rn(x, R10, __fmaf_rn(y, R11, __fmaf_rn(z, R12, ty)));
                PZ[k] = __fmaf_rn(x, R20, __fmaf_rn(y, R21, __fmaf_rn(z, R22, tz)));
                QX[k] = __fmaf_rn(NX[k], R00, __fmaf_rn(NY[k], R01, __fmul_rn(NZ[k], R02)));
                QY[k] = __fmaf_rn(NX[k], R10, __fmaf_rn(NY[k], R11, __fmul_rn(NZ[k], R12)));
                QZ[k] = __fmaf_rn(NX[k], R20, __fmaf_rn(NY[k], R21, __fmul_rn(NZ[k], R22)));
                const float2 q2 = div2_rn(PX[k], PY[k], PZ[k]);
                const float u = __fadd_rn(__fmul_rn(q2.x, fx), cx);
                const float v = __fadd_rn(__fmul_rn(q2.y, fy), cy);
                INV[k] = (u > 0.f) && (u < (float)(W_IMG - 1)) &&
                         (v > 0.f) && (v < (float)(H_IMG - 1));
                const float uif = fminf(fmaxf(rintf(u), 0.f), (float)(W_IMG - 1));
                const float vif = fminf(fmaxf(rintf(v), 0.f), (float)(H_IMG - 1));
                G[k] = (int)vif * W_IMG + (int)uif;
            }

            // Phase C: 24 gathers back-to-back (near-coalesced: ~3 lines each)
            float AX[4], AY[4], AZ[4], BX[4], BY[4], BZ[4];
            #pragma unroll
            for (int k = 0; k < 4; k++) {
                AX[k] = __ldg(v1d + 3 * G[k] + 0);
                AY[k] = __ldg(v1d + 3 * G[k] + 1);
                AZ[k] = __ldg(v1d + 3 * G[k] + 2);
                BX[k] = __ldg(n1d + 3 * G[k] + 0);
                BY[k] = __ldg(n1d + 3 * G[k] + 1);
                BZ[k] = __ldg(n1d + 3 * G[k] + 2);
            }

            // Phase D: residual/Jacobian + branchless accumulate
            #pragma unroll
            for (int k = 0; k < 4; k++) {
                const float px = PX[k], py = PY[k], pz = PZ[k];
                const float bx = BX[k], by = BY[k], bz = BZ[k];
                const float dx = __fadd_rn(px, -AX[k]);
                const float dy = __fadd_rn(py, -AY[k]);
                const float dz = __fadd_rn(pz, -AZ[k]);
                const float d2 = __fmaf_rn(dx, dx, __fmaf_rn(dy, dy, __fmul_rn(dz, dz)));
                const float ndot = __fmaf_rn(QX[k], bx, __fmaf_rn(QY[k], by, __fmul_rn(QZ[k], bz)));

                const bool valid = INV[k] && !(d2 > DIST_THR2_EQ) &&
                                   (Z[k] > 0.f) && (AZ[k] > 0.f) && (ndot > NORM_THR_F);

                float r = __fmaf_rn(bx, dx, __fmaf_rn(by, dy, __fmul_rn(bz, dz)));
                float J[6];
                J[0] = __fadd_rn(__fmul_rn(py, bz), -__fmul_rn(pz, by));
                J[1] = __fadd_rn(__fmul_rn(pz, bx), -__fmul_rn(px, bz));
                J[2] = __fadd_rn(__fmul_rn(px, by), -__fmul_rn(py, bx));
                J[3] = bx; J[4] = by; J[5] = bz;
                if (!valid) {
                    r = 0.f;
                    #pragma unroll
                    for (int q = 0; q < 6; q++) J[q] = 0.f;
                }
                int kk = 0;
                #pragma unroll
                for (int a = 0; a < 6; a++)
                    #pragma unroll
                    for (int c = a; c < 6; c++) { s[kk] = __fmaf_rn(J[a], J[c], s[kk]); kk++; }
                #pragma unroll
                for (int a = 0; a < 6; a++) s[21 + a] = __fmaf_rn(J[a], r, s[21 + a]);
                if (valid) s[27] += 1.f;
            }
        }

        // warp reduction
        #pragma unroll
        for (int i = 0; i < 28; i++) {
            #pragma unroll
            for (int o = 16; o > 0; o >>= 1)
                s[i] += __shfl_down_sync(0xffffffffu, s[i], o);
        }

        if (threadIdx.x < 28) sh[threadIdx.x] = 0.0;
        __syncthreads();
        if ((threadIdx.x & 31) == 0) {
            #pragma unroll
            for (int i = 0; i < 28; i++) atomicAdd(&sh[i], (double)s[i]);
        }
        __syncthreads();
        if (threadIdx.x < 28) atomicAdd(&g_accum[threadIdx.x], sh[threadIdx.x]);

        // ---- grid barrier + inline solve by the last-arriving CTA ----
        if (threadIdx.x == 0) {
            __threadfence();
            s_last = atomicAdd(&g_arrive, 1u);
        }
        __syncthreads();
        const bool is_solver = (s_last == (unsigned)(gridDim.x * (it + 1) - 1));
        if (is_solver && threadIdx.x == 0) {
            solve_update(it == MAX_ITER - 1 ? 1 : 0, out, out_size);
            __threadfence();
            g_phase = it + 1;   // release
        }
        if (it < MAX_ITER - 1) {
            if (threadIdx.x == 0) {
                while (g_phase < (unsigned)(it + 1)) { __nanosleep(200); }
            }
            __syncthreads();
            __threadfence();
        }
    }
}

// ---------------------------------------------------------------------------
extern "C" void kernel_launch(void* const* d_in, const int* in_sizes, int n_in,
                              void* d_out, int out_size)
{
    const float* pose10 = (const float*)d_in[0];
    const float* v0     = (const float*)d_in[1];
    const float* v1     = (const float*)d_in[2];
    const float* n0     = (const float*)d_in[3];
    const float* n1     = (const float*)d_in[4];
    const float* K      = (const float*)d_in[5];
    float* out = (float*)d_out;

    icp_init<<<1, 32>>>(pose10);
    icp_persistent<<<NBLOCKS, NTHREADS>>>(v0, v1, n0, n1, K, out, out_size);
}